// round 10
// baseline (speedup 1.0000x reference)
#include <cuda_runtime.h>
#include <cuda_bf16.h>
#include <math.h>
#include <stdint.h>

// Problem constants
#define BB   32
#define NN   512
#define DIN  768
#define DOUT 256
#define MM   (BB * NN)          // 16384 rows
#define NEGV (-9.0e15f)
#define SLOPE 0.2f

// Scratch (device globals: allocation-free)
__device__ float g_Wh[(size_t)MM * DOUT];   // 16 MB
__device__ float g_s1[MM];
__device__ float g_s2[MM];

// ---------------------------------------------------------------------------
// tf32 helpers
// ---------------------------------------------------------------------------
__device__ __forceinline__ float to_tf32(float x) {
    asm("cvt.rna.tf32.f32 %0, %0;" : "+f"(x));
    return x;
}

__device__ __forceinline__ void mma_tf32(
    float c[4], unsigned a0, unsigned a1, unsigned a2, unsigned a3,
    unsigned b0, unsigned b1)
{
    asm volatile(
        "mma.sync.aligned.m16n8k8.row.col.f32.tf32.tf32.f32 "
        "{%0,%1,%2,%3}, {%4,%5,%6,%7}, {%8,%9}, {%0,%1,%2,%3};\n"
        : "+f"(c[0]), "+f"(c[1]), "+f"(c[2]), "+f"(c[3])
        : "r"(a0), "r"(a1), "r"(a2), "r"(a3), "r"(b0), "r"(b1));
}

// ---------------------------------------------------------------------------
// GEMM tile geometry: BM=128 BN=128 BK=32, 256 threads = 8 warps (4m x 2n),
// warp tile 32x64. SMEM holds FRAGMENT-PACKED operands:
//   A frags: [ks(4)][wg(4)][ms(2)][lane(32)][4]  = 4096 floats (16KB)
//   B frags: [ks(4)][wng(2)][ns(8)][lane(32)][2] = 4096 floats (16KB)
// Mainloop: A = 1 LDS.128 per (ks,ms); B = 1 LDS.64 per (ks,ns); all
// addresses affine in lane (immediate offsets after strength reduction).
// Double buffered: 2 stages x 32KB = 64KB dynamic smem.
// ---------------------------------------------------------------------------
#define BM 128
#define BN 128
#define BK 32
#define STAGE_FLOATS 8192
#define SMEM_BYTES (2 * STAGE_FLOATS * 4)    // 65536

__device__ __forceinline__ int a_frag_off(int m, int k) {
    const int wg = m >> 5, mm = m & 31;
    const int ms = mm >> 4, inner = mm & 15;
    const int gid = inner & 7, selr = inner >> 3;
    const int ks = k >> 3, khalf = (k >> 2) & 1, tid4 = k & 3;
    const int lane = gid * 4 + tid4;
    return ((((ks * 4 + wg) * 2 + ms) * 32 + lane) << 2) + khalf * 2 + selr;
}

__device__ __forceinline__ int b_frag_off(int k, int n) {
    const int wng = n >> 6, nn = n & 63;
    const int ns = nn >> 3, gid = nn & 7;
    const int ks = k >> 3, khalf = (k >> 2) & 1, tid4 = k & 3;
    const int lane = gid * 4 + tid4;
    return (((((ks * 2 + wng) * 8 + ns) * 32) + lane) << 1) + khalf;
}

// scatter staged regs (tf32-rounded) into fragment-packed layout
__device__ __forceinline__ void stage_store(
    float* stage, const float2* ar2, const float4* br4, int t)
{
    float* Af = stage;
    float* Bf = stage + 4096;
    #pragma unroll
    for (int i = 0; i < 8; i++) {
        const int p = t + i * 256;        // 2048 float2 chunks of A (128x32)
        const int r = p >> 4;
        const int c = (p & 15) * 2;
        Af[a_frag_off(r, c)]     = to_tf32(ar2[i].x);
        Af[a_frag_off(r, c + 1)] = to_tf32(ar2[i].y);
    }
    #pragma unroll
    for (int i = 0; i < 4; i++) {
        const int q = t + i * 256;        // 1024 float4 chunks of B (32x128)
        const int kk = q >> 5;
        const int n4 = (q & 31) * 4;
        const float* vv = reinterpret_cast<const float*>(&br4[i]);
        #pragma unroll
        for (int j = 0; j < 4; j++)
            Bf[b_frag_off(kk, n4 + j)] = to_tf32(vv[j]);
    }
}

// mainloop MMAs for one stage, fragment-packed loads
__device__ __forceinline__ void stage_mma(
    const float* stage, float acc[2][8][4], int wg, int wng, int lane)
{
    const float* Af = stage;
    const float* Bf = stage + 4096;
    #pragma unroll
    for (int ks = 0; ks < 4; ks++) {
        const float4 a0 = *reinterpret_cast<const float4*>(
            Af + ((((ks * 4 + wg) * 2 + 0) * 32 + lane) << 2));
        const float4 a1 = *reinterpret_cast<const float4*>(
            Af + ((((ks * 4 + wg) * 2 + 1) * 32 + lane) << 2));
        #pragma unroll
        for (int ns = 0; ns < 8; ns++) {
            const float2 b = *reinterpret_cast<const float2*>(
                Bf + (((((ks * 2 + wng) * 8 + ns) * 32) + lane) << 1));
            const unsigned b0 = __float_as_uint(b.x);
            const unsigned b1 = __float_as_uint(b.y);
            mma_tf32(acc[0][ns],
                __float_as_uint(a0.x), __float_as_uint(a0.y),
                __float_as_uint(a0.z), __float_as_uint(a0.w), b0, b1);
            mma_tf32(acc[1][ns],
                __float_as_uint(a1.x), __float_as_uint(a1.y),
                __float_as_uint(a1.z), __float_as_uint(a1.w), b0, b1);
        }
    }
}

// ---------------------------------------------------------------------------
// Kernel A: Wh = h @ W + pos_table[positions]  (tf32 MMA, packed frags)
// C[16384,256] = A[16384,768] * W[768,256]
// ---------------------------------------------------------------------------
__global__ void __launch_bounds__(256, 2) k_gemm1(
    const float* __restrict__ h,
    const int*   __restrict__ positions,
    const float* __restrict__ W,
    const float* __restrict__ pos_table)
{
    extern __shared__ float smem[];

    const int bx   = blockIdx.x;
    const int row0 = (bx >> 1) * BM;
    const int col0 = (bx & 1)  * BN;

    const int t    = threadIdx.x;
    const int wid  = t >> 5;
    const int lane = t & 31;
    const int gid  = lane >> 2;
    const int tid4 = lane & 3;
    const int wg   = wid & 3;       // m warp group
    const int wng  = wid >> 2;      // n warp group
    const int wm = wg * 32;
    const int wn = wng * 64;

    float acc[2][8][4];
    #pragma unroll
    for (int i = 0; i < 2; i++)
        #pragma unroll
        for (int j = 0; j < 8; j++)
            #pragma unroll
            for (int q = 0; q < 4; q++)
                acc[i][j][q] = 0.f;

    float2 ar2[8];
    float4 br4[4];
    const int a_r  = t >> 4;            // A chunk base row (rows step 16/i? no: p>>4)
    const int a_c  = (t & 15) * 2;
    const int b_kk = t >> 5;
    const int b_n4 = (t & 31) * 4;

    const int NTILES = DIN / BK;   // 24

    // prologue: tile0 -> stage0; tile1 -> regs
    #pragma unroll
    for (int i = 0; i < 8; i++)
        ar2[i] = *reinterpret_cast<const float2*>(
            &h[(size_t)(row0 + a_r + i * 16) * DIN + a_c]);
    #pragma unroll
    for (int i = 0; i < 4; i++)
        br4[i] = *reinterpret_cast<const float4*>(
            &W[(size_t)(b_kk + i * 8) * DOUT + col0 + b_n4]);
    stage_store(smem, ar2, br4, t);
    #pragma unroll
    for (int i = 0; i < 8; i++)
        ar2[i] = *reinterpret_cast<const float2*>(
            &h[(size_t)(row0 + a_r + i * 16) * DIN + BK + a_c]);
    #pragma unroll
    for (int i = 0; i < 4; i++)
        br4[i] = *reinterpret_cast<const float4*>(
            &W[(size_t)(BK + b_kk + i * 8) * DOUT + col0 + b_n4]);
    __syncthreads();

    for (int tile = 0; tile < NTILES; tile++) {
        float* cur = smem + (tile & 1) * STAGE_FLOATS;
        if (tile + 1 < NTILES) {
            float* nxt = smem + ((tile + 1) & 1) * STAGE_FLOATS;
            stage_store(nxt, ar2, br4, t);
        }
        if (tile + 2 < NTILES) {
            const int k0 = (tile + 2) * BK;
            #pragma unroll
            for (int i = 0; i < 8; i++)
                ar2[i] = *reinterpret_cast<const float2*>(
                    &h[(size_t)(row0 + a_r + i * 16) * DIN + k0 + a_c]);
            #pragma unroll
            for (int i = 0; i < 4; i++)
                br4[i] = *reinterpret_cast<const float4*>(
                    &W[(size_t)(k0 + b_kk + i * 8) * DOUT + col0 + b_n4]);
        }
        stage_mma(cur, acc, wg, wng, lane);
        __syncthreads();
    }

    // epilogue: add positional embedding, store Wh
    #pragma unroll
    for (int ms = 0; ms < 2; ms++) {
        const int r0 = row0 + wm + ms * 16 + gid;
        const int r1 = r0 + 8;
        const int p0 = positions[r0];
        const int p1 = positions[r1];
        #pragma unroll
        for (int ns = 0; ns < 8; ns++) {
            const int c = col0 + wn + ns * 8 + tid4 * 2;
            float2 pe0 = *reinterpret_cast<const float2*>(&pos_table[(size_t)p0 * DOUT + c]);
            float2 pe1 = *reinterpret_cast<const float2*>(&pos_table[(size_t)p1 * DOUT + c]);
            float2 o0, o1;
            o0.x = acc[ms][ns][0] + pe0.x;
            o0.y = acc[ms][ns][1] + pe0.y;
            o1.x = acc[ms][ns][2] + pe1.x;
            o1.y = acc[ms][ns][3] + pe1.y;
            *reinterpret_cast<float2*>(&g_Wh[(size_t)r0 * DOUT + c]) = o0;
            *reinterpret_cast<float2*>(&g_Wh[(size_t)r1 * DOUT + c]) = o1;
        }
    }
}

// ---------------------------------------------------------------------------
// Kernel S: s1[row] = Wh[row,:] . a1 ; s2[row] = Wh[row,:] . a2
// ---------------------------------------------------------------------------
__global__ void __launch_bounds__(256) k_sdots(
    const float* __restrict__ a1,
    const float* __restrict__ a2)
{
    const int gwarp = (blockIdx.x * blockDim.x + threadIdx.x) >> 5;
    const int lane  = threadIdx.x & 31;
    if (gwarp >= MM) return;

    const float* wh = g_Wh + (size_t)gwarp * DOUT;
    float p1 = 0.f, p2 = 0.f;
    #pragma unroll
    for (int i = 0; i < 8; i++) {
        const int c = lane + i * 32;
        const float v = wh[c];
        p1 += v * a1[c];
        p2 += v * a2[c];
    }
    #pragma unroll
    for (int off = 16; off; off >>= 1) {
        p1 += __shfl_xor_sync(0xFFFFFFFFu, p1, off);
        p2 += __shfl_xor_sync(0xFFFFFFFFu, p2, off);
    }
    if (lane == 0) {
        g_s1[gwarp] = p1;
        g_s2[gwarp] = p2;
    }
}

// ---------------------------------------------------------------------------
// Kernel SM: masked softmax.  One block = (batch b, 8 rows); warp per row.
// ---------------------------------------------------------------------------
__global__ void __launch_bounds__(256) k_softmax(
    const int* __restrict__ adj,
    float* __restrict__ out_att)
{
    __shared__ float s2s[NN];

    const int b  = blockIdx.x >> 6;
    const int i0 = (blockIdx.x & 63) * 8;
    const int t  = threadIdx.x;

    s2s[t]       = g_s2[b * NN + t];
    s2s[t + 256] = g_s2[b * NN + t + 256];
    __syncthreads();

    const int w = t >> 5, lane = t & 31;
    const int i = i0 + w;
    const float s1v = g_s1[b * NN + i];
    const int* adjrow = adj + (size_t)(b * NN + i) * NN;

    float v[16];
    float m = -INFINITY;
    #pragma unroll
    for (int jj = 0; jj < 16; jj++) {
        const int j = lane + jj * 32;
        const float x = s1v + s2s[j];
        const float e = x > 0.f ? x : SLOPE * x;
        const float val = (adjrow[j] > 0) ? e : NEGV;
        v[jj] = val;
        m = fmaxf(m, val);
    }
    #pragma unroll
    for (int off = 16; off; off >>= 1)
        m = fmaxf(m, __shfl_xor_sync(0xFFFFFFFFu, m, off));

    float s = 0.f;
    #pragma unroll
    for (int jj = 0; jj < 16; jj++) {
        const float ex = __expf(v[jj] - m);
        v[jj] = ex;
        s += ex;
    }
    #pragma unroll
    for (int off = 16; off; off >>= 1)
        s += __shfl_xor_sync(0xFFFFFFFFu, s, off);

    const float inv = 1.f / s;
    float* arow = out_att + (size_t)(b * NN + i) * NN;
    #pragma unroll
    for (int jj = 0; jj < 16; jj++)
        arow[lane + jj * 32] = v[jj] * inv;
}

// ---------------------------------------------------------------------------
// Kernel G2: h_prime[b] = att[b] @ Wh[b]  (tf32 MMA, packed frags)
// per batch: C[512,256] = A[512,512] * B[512,256]
// ---------------------------------------------------------------------------
__global__ void __launch_bounds__(256, 2) k_gemm2(
    const float* __restrict__ att,
    float* __restrict__ out_hp)
{
    extern __shared__ float smem[];

    const int bx   = blockIdx.x;
    const int b    = bx >> 3;
    const int tile = bx & 7;
    const int row0 = (tile >> 1) * BM;
    const int col0 = (tile & 1)  * BN;

    const float* A  = att  + (size_t)b * NN * NN;
    const float* Bm = g_Wh + (size_t)b * NN * DOUT;

    const int t    = threadIdx.x;
    const int wid  = t >> 5;
    const int lane = t & 31;
    const int gid  = lane >> 2;
    const int tid4 = lane & 3;
    const int wg   = wid & 3;
    const int wng  = wid >> 2;
    const int wm = wg * 32;
    const int wn = wng * 64;

    float acc[2][8][4];
    #pragma unroll
    for (int i = 0; i < 2; i++)
        #pragma unroll
        for (int j = 0; j < 8; j++)
            #pragma unroll
            for (int q = 0; q < 4; q++)
                acc[i][j][q] = 0.f;

    float2 ar2[8];
    float4 br4[4];
    const int a_r  = t >> 4;
    const int a_c  = (t & 15) * 2;
    const int b_kk = t >> 5;
    const int b_n4 = (t & 31) * 4;

    const int NTILES = NN / BK;    // 16

    #pragma unroll
    for (int i = 0; i < 8; i++)
        ar2[i] = *reinterpret_cast<const float2*>(
            &A[(size_t)(row0 + a_r + i * 16) * NN + a_c]);
    #pragma unroll
    for (int i = 0; i < 4; i++)
        br4[i] = *reinterpret_cast<const float4*>(
            &Bm[(size_t)(b_kk + i * 8) * DOUT + col0 + b_n4]);
    stage_store(smem, ar2, br4, t);
    #pragma unroll
    for (int i = 0; i < 8; i++)
        ar2[i] = *reinterpret_cast<const float2*>(
            &A[(size_t)(row0 + a_r + i * 16) * NN + BK + a_c]);
    #pragma unroll
    for (int i = 0; i < 4; i++)
        br4[i] = *reinterpret_cast<const float4*>(
            &Bm[(size_t)(BK + b_kk + i * 8) * DOUT + col0 + b_n4]);
    __syncthreads();

    for (int tk = 0; tk < NTILES; tk++) {
        float* cur = smem + (tk & 1) * STAGE_FLOATS;
        if (tk + 1 < NTILES) {
            float* nxt = smem + ((tk + 1) & 1) * STAGE_FLOATS;
            stage_store(nxt, ar2, br4, t);
        }
        if (tk + 2 < NTILES) {
            const int k0 = (tk + 2) * BK;
            #pragma unroll
            for (int i = 0; i < 8; i++)
                ar2[i] = *reinterpret_cast<const float2*>(
                    &A[(size_t)(row0 + a_r + i * 16) * NN + k0 + a_c]);
            #pragma unroll
            for (int i = 0; i < 4; i++)
                br4[i] = *reinterpret_cast<const float4*>(
                    &Bm[(size_t)(k0 + b_kk + i * 8) * DOUT + col0 + b_n4]);
        }
        stage_mma(cur, acc, wg, wng, lane);
        __syncthreads();
    }

    float* outB = out_hp + (size_t)b * NN * DOUT;
    #pragma unroll
    for (int ms = 0; ms < 2; ms++) {
        const int r0 = row0 + wm + ms * 16 + gid;
        const int r1 = r0 + 8;
        #pragma unroll
        for (int ns = 0; ns < 8; ns++) {
            const int c = col0 + wn + ns * 8 + tid4 * 2;
            float2 o0, o1;
            o0.x = acc[ms][ns][0];
            o0.y = acc[ms][ns][1];
            o1.x = acc[ms][ns][2];
            o1.y = acc[ms][ns][3];
            *reinterpret_cast<float2*>(&outB[(size_t)r0 * DOUT + c]) = o0;
            *reinterpret_cast<float2*>(&outB[(size_t)r1 * DOUT + c]) = o1;
        }
    }
}

// ---------------------------------------------------------------------------
extern "C" void kernel_launch(void* const* d_in, const int* in_sizes, int n_in,
                              void* d_out, int out_size)
{
    const float* h         = (const float*)d_in[0];
    const int*   adj       = (const int*)  d_in[1];
    const int*   positions = (const int*)  d_in[2];
    const float* W         = (const float*)d_in[3];
    const float* a1        = (const float*)d_in[4];
    const float* a2        = (const float*)d_in[5];
    const float* pos_table = (const float*)d_in[6];

    float* out_hp  = (float*)d_out;                        // [B,N,DOUT]
    float* out_att = (float*)d_out + (size_t)MM * DOUT;    // [B,N,N]

    static bool attr_done = false;
    if (!attr_done) {
        cudaFuncSetAttribute(k_gemm1,
            cudaFuncAttributeMaxDynamicSharedMemorySize, SMEM_BYTES);
        cudaFuncSetAttribute(k_gemm2,
            cudaFuncAttributeMaxDynamicSharedMemorySize, SMEM_BYTES);
        attr_done = true;
    }

    k_gemm1<<<(MM / BM) * (DOUT / BN), 256, SMEM_BYTES>>>(h, positions, W, pos_table);
    k_sdots<<<MM / 8, 256>>>(a1, a2);
    k_softmax<<<BB * (NN / 8), 256>>>(adj, out_att);
    k_gemm2<<<BB * 8, 256, SMEM_BYTES>>>(out_att, out_hp);
}

// round 11
// speedup vs baseline: 2.1947x; 2.1947x over previous
#include <cuda_runtime.h>
#include <cuda_bf16.h>
#include <math.h>
#include <stdint.h>

// Problem constants
#define BB   32
#define NN   512
#define DIN  768
#define DOUT 256
#define MM   (BB * NN)          // 16384 rows
#define NEGV (-9.0e15f)
#define SLOPE 0.2f

// Scratch (device globals: allocation-free)
__device__ float g_Wh[(size_t)MM * DOUT];   // 16 MB
__device__ float g_s1[MM];
__device__ float g_s2[MM];

// ---------------------------------------------------------------------------
// tf32 helpers
// ---------------------------------------------------------------------------
__device__ __forceinline__ float to_tf32(float x) {
    asm("cvt.rna.tf32.f32 %0, %0;" : "+f"(x));
    return x;
}

__device__ __forceinline__ void mma_tf32(
    float c[4], unsigned a0, unsigned a1, unsigned a2, unsigned a3,
    unsigned b0, unsigned b1)
{
    asm volatile(
        "mma.sync.aligned.m16n8k8.row.col.f32.tf32.tf32.f32 "
        "{%0,%1,%2,%3}, {%4,%5,%6,%7}, {%8,%9}, {%0,%1,%2,%3};\n"
        : "+f"(c[0]), "+f"(c[1]), "+f"(c[2]), "+f"(c[3])
        : "r"(a0), "r"(a1), "r"(a2), "r"(a3), "r"(b0), "r"(b1));
}

// ---------------------------------------------------------------------------
// GEMM tile geometry: BM=64 BN=128 BK=32, 256 threads = 8 warps (2m x 4n),
// warp tile 32x32 (acc = 32 regs) -> target 3 CTAs/SM.
// SMEM layout identical in style to the verified R8 kernel:
//   As[64][36], Bs[32][136], conflict-free frag loads, float4 staging.
// Double buffered: 2 stages x 26KB = 53KB dynamic smem.
// ---------------------------------------------------------------------------
#define BM 64
#define BN 128
#define BK 32
#define ASTRIDE 36
#define BSTRIDE 136
#define AS_FLOATS (BM * ASTRIDE)                 // 2304
#define BS_FLOATS (BK * BSTRIDE)                 // 4352
#define STAGE_FLOATS (AS_FLOATS + BS_FLOATS)     // 6656
#define SMEM_BYTES (2 * STAGE_FLOATS * 4)        // 53248

// store staged regs (with tf32 rounding) into a given stage
__device__ __forceinline__ void stage_store(
    float* stage, const float4* ar, const float4* br,
    int a_m, int a_k4, int b_kr, int b_n4)
{
    float (*As)[ASTRIDE] = reinterpret_cast<float (*)[ASTRIDE]>(stage);
    float (*Bs)[BSTRIDE] = reinterpret_cast<float (*)[BSTRIDE]>(stage + AS_FLOATS);
    #pragma unroll
    for (int i = 0; i < 2; i++) {
        float4 v = ar[i];
        v.x = to_tf32(v.x); v.y = to_tf32(v.y);
        v.z = to_tf32(v.z); v.w = to_tf32(v.w);
        *reinterpret_cast<float4*>(&As[a_m + i * 32][a_k4]) = v;
    }
    #pragma unroll
    for (int i = 0; i < 4; i++) {
        float4 w4 = br[i];
        w4.x = to_tf32(w4.x); w4.y = to_tf32(w4.y);
        w4.z = to_tf32(w4.z); w4.w = to_tf32(w4.w);
        *reinterpret_cast<float4*>(&Bs[b_kr + i * 8][b_n4]) = w4;
    }
}

// run the 4 k-steps of MMAs for one stage (warp tile 32x32)
__device__ __forceinline__ void stage_mma(
    const float* stage, float acc[2][4][4],
    int wm, int wn, int gid, int tid4)
{
    const float (*As)[ASTRIDE] =
        reinterpret_cast<const float (*)[ASTRIDE]>(stage);
    const float (*Bs)[BSTRIDE] =
        reinterpret_cast<const float (*)[BSTRIDE]>(stage + AS_FLOATS);
    #pragma unroll
    for (int ks = 0; ks < 4; ks++) {
        const int k8 = ks * 8;
        unsigned af[2][4];
        #pragma unroll
        for (int ms = 0; ms < 2; ms++) {
            const int r = wm + ms * 16 + gid;
            af[ms][0] = __float_as_uint(As[r    ][k8 + tid4]);
            af[ms][1] = __float_as_uint(As[r + 8][k8 + tid4]);
            af[ms][2] = __float_as_uint(As[r    ][k8 + tid4 + 4]);
            af[ms][3] = __float_as_uint(As[r + 8][k8 + tid4 + 4]);
        }
        #pragma unroll
        for (int ns = 0; ns < 4; ns++) {
            const int c = wn + ns * 8 + gid;
            unsigned b0 = __float_as_uint(Bs[k8 + tid4    ][c]);
            unsigned b1 = __float_as_uint(Bs[k8 + tid4 + 4][c]);
            mma_tf32(acc[0][ns], af[0][0], af[0][1], af[0][2], af[0][3], b0, b1);
            mma_tf32(acc[1][ns], af[1][0], af[1][1], af[1][2], af[1][3], b0, b1);
        }
    }
}

// ---------------------------------------------------------------------------
// Kernel A: Wh = h @ W + pos_table[positions]  (tf32 MMA, 2-stage pipeline)
// C[16384,256] = A[16384,768] * W[768,256]
// grid: 256 row-tiles x 2 col-tiles = 512
// ---------------------------------------------------------------------------
__global__ void __launch_bounds__(256, 3) k_gemm1(
    const float* __restrict__ h,
    const int*   __restrict__ positions,
    const float* __restrict__ W,
    const float* __restrict__ pos_table)
{
    extern __shared__ float smem[];

    const int bx   = blockIdx.x;
    const int row0 = (bx >> 1) * BM;
    const int col0 = (bx & 1)  * BN;

    const int t    = threadIdx.x;
    const int wid  = t >> 5;
    const int lane = t & 31;
    const int gid  = lane >> 2;
    const int tid4 = lane & 3;
    const int wg   = wid & 1;       // m warp group (0..1)
    const int wng  = wid >> 1;      // n warp group (0..3)
    const int wm = wg * 32;
    const int wn = wng * 32;

    float acc[2][4][4];
    #pragma unroll
    for (int i = 0; i < 2; i++)
        #pragma unroll
        for (int j = 0; j < 4; j++)
            #pragma unroll
            for (int q = 0; q < 4; q++)
                acc[i][j][q] = 0.f;

    float4 ar[2], br[4];
    const int a_m  = t >> 3;            // rows advance by 32 per chunk
    const int a_k4 = (t & 7) * 4;
    const int b_kr = t >> 5;            // k rows advance by 8 per chunk
    const int b_n4 = (t & 31) * 4;

    const int NTILES = DIN / BK;   // 24

    // prologue: tile0 -> stage0; tile1 -> regs
    #pragma unroll
    for (int i = 0; i < 2; i++)
        ar[i] = *reinterpret_cast<const float4*>(
            &h[(size_t)(row0 + a_m + i * 32) * DIN + a_k4]);
    #pragma unroll
    for (int i = 0; i < 4; i++)
        br[i] = *reinterpret_cast<const float4*>(
            &W[(size_t)(b_kr + i * 8) * DOUT + col0 + b_n4]);
    stage_store(smem, ar, br, a_m, a_k4, b_kr, b_n4);
    #pragma unroll
    for (int i = 0; i < 2; i++)
        ar[i] = *reinterpret_cast<const float4*>(
            &h[(size_t)(row0 + a_m + i * 32) * DIN + BK + a_k4]);
    #pragma unroll
    for (int i = 0; i < 4; i++)
        br[i] = *reinterpret_cast<const float4*>(
            &W[(size_t)(BK + b_kr + i * 8) * DOUT + col0 + b_n4]);
    __syncthreads();

    for (int tile = 0; tile < NTILES; tile++) {
        float* cur = smem + (tile & 1) * STAGE_FLOATS;
        if (tile + 1 < NTILES) {
            float* nxt = smem + ((tile + 1) & 1) * STAGE_FLOATS;
            stage_store(nxt, ar, br, a_m, a_k4, b_kr, b_n4);
        }
        if (tile + 2 < NTILES) {
            const int k0 = (tile + 2) * BK;
            #pragma unroll
            for (int i = 0; i < 2; i++)
                ar[i] = *reinterpret_cast<const float4*>(
                    &h[(size_t)(row0 + a_m + i * 32) * DIN + k0 + a_k4]);
            #pragma unroll
            for (int i = 0; i < 4; i++)
                br[i] = *reinterpret_cast<const float4*>(
                    &W[(size_t)(k0 + b_kr + i * 8) * DOUT + col0 + b_n4]);
        }
        stage_mma(cur, acc, wm, wn, gid, tid4);
        __syncthreads();
    }

    // epilogue: add positional embedding, store Wh
    #pragma unroll
    for (int ms = 0; ms < 2; ms++) {
        const int r0 = row0 + wm + ms * 16 + gid;
        const int r1 = r0 + 8;
        const int p0 = positions[r0];
        const int p1 = positions[r1];
        #pragma unroll
        for (int ns = 0; ns < 4; ns++) {
            const int c = col0 + wn + ns * 8 + tid4 * 2;
            float2 pe0 = *reinterpret_cast<const float2*>(&pos_table[(size_t)p0 * DOUT + c]);
            float2 pe1 = *reinterpret_cast<const float2*>(&pos_table[(size_t)p1 * DOUT + c]);
            float2 o0, o1;
            o0.x = acc[ms][ns][0] + pe0.x;
            o0.y = acc[ms][ns][1] + pe0.y;
            o1.x = acc[ms][ns][2] + pe1.x;
            o1.y = acc[ms][ns][3] + pe1.y;
            *reinterpret_cast<float2*>(&g_Wh[(size_t)r0 * DOUT + c]) = o0;
            *reinterpret_cast<float2*>(&g_Wh[(size_t)r1 * DOUT + c]) = o1;
        }
    }
}

// ---------------------------------------------------------------------------
// Kernel S: s1[row] = Wh[row,:] . a1 ; s2[row] = Wh[row,:] . a2
// ---------------------------------------------------------------------------
__global__ void __launch_bounds__(256) k_sdots(
    const float* __restrict__ a1,
    const float* __restrict__ a2)
{
    const int gwarp = (blockIdx.x * blockDim.x + threadIdx.x) >> 5;
    const int lane  = threadIdx.x & 31;
    if (gwarp >= MM) return;

    const float* wh = g_Wh + (size_t)gwarp * DOUT;
    float p1 = 0.f, p2 = 0.f;
    #pragma unroll
    for (int i = 0; i < 8; i++) {
        const int c = lane + i * 32;
        const float v = wh[c];
        p1 += v * a1[c];
        p2 += v * a2[c];
    }
    #pragma unroll
    for (int off = 16; off; off >>= 1) {
        p1 += __shfl_xor_sync(0xFFFFFFFFu, p1, off);
        p2 += __shfl_xor_sync(0xFFFFFFFFu, p2, off);
    }
    if (lane == 0) {
        g_s1[gwarp] = p1;
        g_s2[gwarp] = p2;
    }
}

// ---------------------------------------------------------------------------
// Kernel SM: masked softmax.  One block = (batch b, 8 rows); warp per row.
// ---------------------------------------------------------------------------
__global__ void __launch_bounds__(256) k_softmax(
    const int* __restrict__ adj,
    float* __restrict__ out_att)
{
    __shared__ float s2s[NN];

    const int b  = blockIdx.x >> 6;
    const int i0 = (blockIdx.x & 63) * 8;
    const int t  = threadIdx.x;

    s2s[t]       = g_s2[b * NN + t];
    s2s[t + 256] = g_s2[b * NN + t + 256];
    __syncthreads();

    const int w = t >> 5, lane = t & 31;
    const int i = i0 + w;
    const float s1v = g_s1[b * NN + i];
    const int* adjrow = adj + (size_t)(b * NN + i) * NN;

    float v[16];
    float m = -INFINITY;
    #pragma unroll
    for (int jj = 0; jj < 16; jj++) {
        const int j = lane + jj * 32;
        const float x = s1v + s2s[j];
        const float e = x > 0.f ? x : SLOPE * x;
        const float val = (adjrow[j] > 0) ? e : NEGV;
        v[jj] = val;
        m = fmaxf(m, val);
    }
    #pragma unroll
    for (int off = 16; off; off >>= 1)
        m = fmaxf(m, __shfl_xor_sync(0xFFFFFFFFu, m, off));

    float s = 0.f;
    #pragma unroll
    for (int jj = 0; jj < 16; jj++) {
        const float ex = __expf(v[jj] - m);
        v[jj] = ex;
        s += ex;
    }
    #pragma unroll
    for (int off = 16; off; off >>= 1)
        s += __shfl_xor_sync(0xFFFFFFFFu, s, off);

    const float inv = 1.f / s;
    float* arow = out_att + (size_t)(b * NN + i) * NN;
    #pragma unroll
    for (int jj = 0; jj < 16; jj++)
        arow[lane + jj * 32] = v[jj] * inv;
}

// ---------------------------------------------------------------------------
// Kernel G2: h_prime[b] = att[b] @ Wh[b]  (tf32 MMA, 2-stage pipeline)
// per batch: C[512,256] = A[512,512] * B[512,256]
// grid: 32 batches x 8 row-tiles x 2 col-tiles = 512
// ---------------------------------------------------------------------------
__global__ void __launch_bounds__(256, 3) k_gemm2(
    const float* __restrict__ att,
    float* __restrict__ out_hp)
{
    extern __shared__ float smem[];

    const int bx   = blockIdx.x;
    const int b    = bx >> 4;
    const int tile = bx & 15;
    const int row0 = (tile >> 1) * BM;
    const int col0 = (tile & 1)  * BN;

    const float* A  = att  + (size_t)b * NN * NN;
    const float* Bm = g_Wh + (size_t)b * NN * DOUT;

    const int t    = threadIdx.x;
    const int wid  = t >> 5;
    const int lane = t & 31;
    const int gid  = lane >> 2;
    const int tid4 = lane & 3;
    const int wg   = wid & 1;
    const int wng  = wid >> 1;
    const int wm = wg * 32;
    const int wn = wng * 32;

    float acc[2][4][4];
    #pragma unroll
    for (int i = 0; i < 2; i++)
        #pragma unroll
        for (int j = 0; j < 4; j++)
            #pragma unroll
            for (int q = 0; q < 4; q++)
                acc[i][j][q] = 0.f;

    float4 ar[2], br[4];
    const int a_m  = t >> 3;
    const int a_k4 = (t & 7) * 4;
    const int b_kr = t >> 5;
    const int b_n4 = (t & 31) * 4;

    const int NTILES = NN / BK;    // 16

    #pragma unroll
    for (int i = 0; i < 2; i++)
        ar[i] = *reinterpret_cast<const float4*>(
            &A[(size_t)(row0 + a_m + i * 32) * NN + a_k4]);
    #pragma unroll
    for (int i = 0; i < 4; i++)
        br[i] = *reinterpret_cast<const float4*>(
            &Bm[(size_t)(b_kr + i * 8) * DOUT + col0 + b_n4]);
    stage_store(smem, ar, br, a_m, a_k4, b_kr, b_n4);
    #pragma unroll
    for (int i = 0; i < 2; i++)
        ar[i] = *reinterpret_cast<const float4*>(
            &A[(size_t)(row0 + a_m + i * 32) * NN + BK + a_k4]);
    #pragma unroll
    for (int i = 0; i < 4; i++)
        br[i] = *reinterpret_cast<const float4*>(
            &Bm[(size_t)(BK + b_kr + i * 8) * DOUT + col0 + b_n4]);
    __syncthreads();

    for (int tk = 0; tk < NTILES; tk++) {
        float* cur = smem + (tk & 1) * STAGE_FLOATS;
        if (tk + 1 < NTILES) {
            float* nxt = smem + ((tk + 1) & 1) * STAGE_FLOATS;
            stage_store(nxt, ar, br, a_m, a_k4, b_kr, b_n4);
        }
        if (tk + 2 < NTILES) {
            const int k0 = (tk + 2) * BK;
            #pragma unroll
            for (int i = 0; i < 2; i++)
                ar[i] = *reinterpret_cast<const float4*>(
                    &A[(size_t)(row0 + a_m + i * 32) * NN + k0 + a_k4]);
            #pragma unroll
            for (int i = 0; i < 4; i++)
                br[i] = *reinterpret_cast<const float4*>(
                    &Bm[(size_t)(k0 + b_kr + i * 8) * DOUT + col0 + b_n4]);
        }
        stage_mma(cur, acc, wm, wn, gid, tid4);
        __syncthreads();
    }

    float* outB = out_hp + (size_t)b * NN * DOUT;
    #pragma unroll
    for (int ms = 0; ms < 2; ms++) {
        const int r0 = row0 + wm + ms * 16 + gid;
        const int r1 = r0 + 8;
        #pragma unroll
        for (int ns = 0; ns < 4; ns++) {
            const int c = col0 + wn + ns * 8 + tid4 * 2;
            float2 o0, o1;
            o0.x = acc[ms][ns][0];
            o0.y = acc[ms][ns][1];
            o1.x = acc[ms][ns][2];
            o1.y = acc[ms][ns][3];
            *reinterpret_cast<float2*>(&outB[(size_t)r0 * DOUT + c]) = o0;
            *reinterpret_cast<float2*>(&outB[(size_t)r1 * DOUT + c]) = o1;
        }
    }
}

// ---------------------------------------------------------------------------
extern "C" void kernel_launch(void* const* d_in, const int* in_sizes, int n_in,
                              void* d_out, int out_size)
{
    const float* h         = (const float*)d_in[0];
    const int*   adj       = (const int*)  d_in[1];
    const int*   positions = (const int*)  d_in[2];
    const float* W         = (const float*)d_in[3];
    const float* a1        = (const float*)d_in[4];
    const float* a2        = (const float*)d_in[5];
    const float* pos_table = (const float*)d_in[6];

    float* out_hp  = (float*)d_out;                        // [B,N,DOUT]
    float* out_att = (float*)d_out + (size_t)MM * DOUT;    // [B,N,N]

    static bool attr_done = false;
    if (!attr_done) {
        cudaFuncSetAttribute(k_gemm1,
            cudaFuncAttributeMaxDynamicSharedMemorySize, SMEM_BYTES);
        cudaFuncSetAttribute(k_gemm2,
            cudaFuncAttributeMaxDynamicSharedMemorySize, SMEM_BYTES);
        attr_done = true;
    }

    k_gemm1<<<(MM / BM) * (DOUT / BN), 256, SMEM_BYTES>>>(h, positions, W, pos_table);
    k_sdots<<<MM / 8, 256>>>(a1, a2);
    k_softmax<<<BB * (NN / 8), 256>>>(adj, out_att);
    k_gemm2<<<BB * 16, 256, SMEM_BYTES>>>(out_att, out_hp);
}

// round 12
// speedup vs baseline: 2.5728x; 1.1723x over previous
#include <cuda_runtime.h>
#include <cuda_fp16.h>
#include <math.h>
#include <stdint.h>

// Problem constants
#define BB   32
#define NN   512
#define DIN  768
#define DOUT 256
#define MM   (BB * NN)          // 16384 rows
#define NEGV (-9.0e15f)
#define SLOPE 0.2f

// Scratch (device globals: allocation-free)
__device__ float  g_Wh[(size_t)MM * DOUT];          // 16 MB fp32
__device__ float  g_s1[MM];
__device__ float  g_s2[MM];
__device__ __half g_h16[(size_t)MM * DIN];          // 24 MB: h in fp16
__device__ __half g_Wt16[(size_t)DOUT * DIN];       // W^T  [256][768] fp16
__device__ __half g_Wht16[(size_t)BB * DOUT * NN];  // Wh^T [b][256][512] fp16
__device__ __half g_att16[(size_t)BB * NN * NN];    // att  [b][512][512] fp16

// ---------------------------------------------------------------------------
// fp16 MMA helper: m16n8k16, fp32 accumulate
// ---------------------------------------------------------------------------
__device__ __forceinline__ void mma_f16(
    float c[4], unsigned a0, unsigned a1, unsigned a2, unsigned a3,
    unsigned b0, unsigned b1)
{
    asm volatile(
        "mma.sync.aligned.m16n8k16.row.col.f32.f16.f16.f32 "
        "{%0,%1,%2,%3}, {%4,%5,%6,%7}, {%8,%9}, {%0,%1,%2,%3};\n"
        : "+f"(c[0]), "+f"(c[1]), "+f"(c[2]), "+f"(c[3])
        : "r"(a0), "r"(a1), "r"(a2), "r"(a3), "r"(b0), "r"(b1));
}

// ---------------------------------------------------------------------------
// GEMM tile geometry: BM=128 BN=128 BK=32, 8 warps (4m x 2n), warp tile 32x64.
// SMEM: A as [m(128)][k-pairs(16 u32) + pad4]  (u32 = half2 of k,k+1)
//       B as [n(128)][k-pairs(16 u32) + pad4]
// stride 20 u32 -> all fragment loads bank-conflict-free.
// Double buffered: 2 stages x 20KB = 40KB dynamic smem.
// ---------------------------------------------------------------------------
#define BM 128
#define BN 128
#define BK 32
#define RSTRIDE 20                     // u32 per row (16 data + 4 pad)
#define A_U32   (BM * RSTRIDE)         // 2560
#define STAGE_U32 (2 * A_U32)          // A + B = 5120
#define SMEM_BYTES (2 * STAGE_U32 * 4) // 40960

// stage copy: 2 uint4 for A + 2 uint4 for B per thread
__device__ __forceinline__ void stage_store(
    unsigned* stage, const uint4* av, const uint4* bv, int rr, int uu)
{
    #pragma unroll
    for (int i = 0; i < 2; i++)
        *reinterpret_cast<uint4*>(stage + (rr + i * 64) * RSTRIDE + uu * 4) = av[i];
    #pragma unroll
    for (int i = 0; i < 2; i++)
        *reinterpret_cast<uint4*>(stage + A_U32 + (rr + i * 64) * RSTRIDE + uu * 4) = bv[i];
}

// mainloop: 2 k16-steps, warp tile 32x64
__device__ __forceinline__ void stage_mma(
    const unsigned* stage, float acc[2][8][4], int wm, int wn, int gid, int tid4)
{
    const unsigned* Aq = stage;
    const unsigned* Bq = stage + A_U32;
    #pragma unroll
    for (int ks = 0; ks < 2; ks++) {
        const int kc = ks * 8 + tid4;
        unsigned a[2][4];
        #pragma unroll
        for (int ms = 0; ms < 2; ms++) {
            const int r = wm + ms * 16 + gid;
            a[ms][0] = Aq[r * RSTRIDE + kc];
            a[ms][1] = Aq[(r + 8) * RSTRIDE + kc];
            a[ms][2] = Aq[r * RSTRIDE + kc + 4];
            a[ms][3] = Aq[(r + 8) * RSTRIDE + kc + 4];
        }
        #pragma unroll
        for (int ns = 0; ns < 8; ns++) {
            const int c = wn + ns * 8 + gid;
            const unsigned b0 = Bq[c * RSTRIDE + kc];
            const unsigned b1 = Bq[c * RSTRIDE + kc + 4];
            mma_f16(acc[0][ns], a[0][0], a[0][1], a[0][2], a[0][3], b0, b1);
            mma_f16(acc[1][ns], a[1][0], a[1][1], a[1][2], a[1][3], b0, b1);
        }
    }
}

// ---------------------------------------------------------------------------
// prep kernels
// ---------------------------------------------------------------------------
__global__ void __launch_bounds__(256) k_prep_h(const float* __restrict__ h)
{
    const int idx = blockIdx.x * 256 + threadIdx.x;   // float4 index
    float4 v = reinterpret_cast<const float4*>(h)[idx];
    __half2 p0 = __floats2half2_rn(v.x, v.y);
    __half2 p1 = __floats2half2_rn(v.z, v.w);
    uint2 o;
    o.x = *reinterpret_cast<unsigned*>(&p0);
    o.y = *reinterpret_cast<unsigned*>(&p1);
    reinterpret_cast<uint2*>(g_h16)[idx] = o;
}

__global__ void k_prep_w(const float* __restrict__ W)
{
    __shared__ float tile[32][33];
    const int k0 = blockIdx.x * 32;
    const int n0 = blockIdx.y * 32;
    const int tx = threadIdx.x, ty = threadIdx.y;
    #pragma unroll
    for (int j = 0; j < 4; j++)
        tile[ty + j * 8][tx] = W[(size_t)(k0 + ty + j * 8) * DOUT + n0 + tx];
    __syncthreads();
    #pragma unroll
    for (int j = 0; j < 4; j++)
        g_Wt16[(size_t)(n0 + ty + j * 8) * DIN + k0 + tx] =
            __float2half_rn(tile[tx][ty + j * 8]);
}

__global__ void k_prep_wht()
{
    __shared__ float tile[32][33];
    const int b  = blockIdx.x >> 7;
    const int r  = blockIdx.x & 127;
    const int j0 = (r >> 3) * 32;    // 16 j-tiles
    const int d0 = (r & 7) * 32;     // 8 d-tiles
    const int tx = threadIdx.x, ty = threadIdx.y;
    #pragma unroll
    for (int j = 0; j < 4; j++)
        tile[ty + j * 8][tx] =
            g_Wh[((size_t)b * NN + j0 + ty + j * 8) * DOUT + d0 + tx];
    __syncthreads();
    #pragma unroll
    for (int j = 0; j < 4; j++)
        g_Wht16[((size_t)b * DOUT + d0 + ty + j * 8) * NN + j0 + tx] =
            __float2half_rn(tile[tx][ty + j * 8]);
}

// ---------------------------------------------------------------------------
// Kernel A: Wh = h @ W + pos_table[positions]   (fp16 MMA, 2-stage pipeline)
// C[16384,256] = A[16384,768] * W[768,256];  grid 128x2 = 256 CTAs
// ---------------------------------------------------------------------------
__global__ void __launch_bounds__(256, 2) k_gemm1(
    const int*   __restrict__ positions,
    const float* __restrict__ pos_table)
{
    extern __shared__ unsigned smem[];

    const int bx   = blockIdx.x;
    const int row0 = (bx >> 1) * BM;
    const int col0 = (bx & 1)  * BN;

    const int t    = threadIdx.x;
    const int wid  = t >> 5;
    const int lane = t & 31;
    const int gid  = lane >> 2;
    const int tid4 = lane & 3;
    const int wg   = wid & 3;
    const int wng  = wid >> 2;
    const int wm = wg * 32;
    const int wn = wng * 64;

    float acc[2][8][4];
    #pragma unroll
    for (int i = 0; i < 2; i++)
        #pragma unroll
        for (int j = 0; j < 8; j++)
            #pragma unroll
            for (int q = 0; q < 4; q++)
                acc[i][j][q] = 0.f;

    uint4 av[2], bv[2];
    const int rr = t >> 2;        // 0..63 (rows advance by 64 per chunk)
    const int uu = t & 3;         // uint4 within row

    const int NTILES = DIN / BK;  // 24

    // prologue
    #pragma unroll
    for (int i = 0; i < 2; i++) {
        av[i] = *reinterpret_cast<const uint4*>(
            g_h16 + (size_t)(row0 + rr + i * 64) * DIN + uu * 8);
        bv[i] = *reinterpret_cast<const uint4*>(
            g_Wt16 + (size_t)(col0 + rr + i * 64) * DIN + uu * 8);
    }
    stage_store(smem, av, bv, rr, uu);
    #pragma unroll
    for (int i = 0; i < 2; i++) {
        av[i] = *reinterpret_cast<const uint4*>(
            g_h16 + (size_t)(row0 + rr + i * 64) * DIN + BK + uu * 8);
        bv[i] = *reinterpret_cast<const uint4*>(
            g_Wt16 + (size_t)(col0 + rr + i * 64) * DIN + BK + uu * 8);
    }
    __syncthreads();

    for (int tile = 0; tile < NTILES; tile++) {
        unsigned* cur = smem + (tile & 1) * STAGE_U32;
        if (tile + 1 < NTILES) {
            unsigned* nxt = smem + ((tile + 1) & 1) * STAGE_U32;
            stage_store(nxt, av, bv, rr, uu);
        }
        if (tile + 2 < NTILES) {
            const int k0 = (tile + 2) * BK;
            #pragma unroll
            for (int i = 0; i < 2; i++) {
                av[i] = *reinterpret_cast<const uint4*>(
                    g_h16 + (size_t)(row0 + rr + i * 64) * DIN + k0 + uu * 8);
                bv[i] = *reinterpret_cast<const uint4*>(
                    g_Wt16 + (size_t)(col0 + rr + i * 64) * DIN + k0 + uu * 8);
            }
        }
        stage_mma(cur, acc, wm, wn, gid, tid4);
        __syncthreads();
    }

    // epilogue: add positional embedding, store Wh (fp32)
    #pragma unroll
    for (int ms = 0; ms < 2; ms++) {
        const int r0 = row0 + wm + ms * 16 + gid;
        const int r1 = r0 + 8;
        const int p0 = positions[r0];
        const int p1 = positions[r1];
        #pragma unroll
        for (int ns = 0; ns < 8; ns++) {
            const int c = col0 + wn + ns * 8 + tid4 * 2;
            float2 pe0 = *reinterpret_cast<const float2*>(&pos_table[(size_t)p0 * DOUT + c]);
            float2 pe1 = *reinterpret_cast<const float2*>(&pos_table[(size_t)p1 * DOUT + c]);
            float2 o0, o1;
            o0.x = acc[ms][ns][0] + pe0.x;
            o0.y = acc[ms][ns][1] + pe0.y;
            o1.x = acc[ms][ns][2] + pe1.x;
            o1.y = acc[ms][ns][3] + pe1.y;
            *reinterpret_cast<float2*>(&g_Wh[(size_t)r0 * DOUT + c]) = o0;
            *reinterpret_cast<float2*>(&g_Wh[(size_t)r1 * DOUT + c]) = o1;
        }
    }
}

// ---------------------------------------------------------------------------
// Kernel S: s1/s2 row dots
// ---------------------------------------------------------------------------
__global__ void __launch_bounds__(256) k_sdots(
    const float* __restrict__ a1,
    const float* __restrict__ a2)
{
    const int gwarp = (blockIdx.x * blockDim.x + threadIdx.x) >> 5;
    const int lane  = threadIdx.x & 31;
    if (gwarp >= MM) return;

    const float* wh = g_Wh + (size_t)gwarp * DOUT;
    float p1 = 0.f, p2 = 0.f;
    #pragma unroll
    for (int i = 0; i < 8; i++) {
        const int c = lane + i * 32;
        const float v = wh[c];
        p1 += v * a1[c];
        p2 += v * a2[c];
    }
    #pragma unroll
    for (int off = 16; off; off >>= 1) {
        p1 += __shfl_xor_sync(0xFFFFFFFFu, p1, off);
        p2 += __shfl_xor_sync(0xFFFFFFFFu, p2, off);
    }
    if (lane == 0) {
        g_s1[gwarp] = p1;
        g_s2[gwarp] = p2;
    }
}

// ---------------------------------------------------------------------------
// Kernel SM: masked softmax; writes fp32 att output + fp16 copy
// ---------------------------------------------------------------------------
__global__ void __launch_bounds__(256) k_softmax(
    const int* __restrict__ adj,
    float* __restrict__ out_att)
{
    __shared__ float s2s[NN];

    const int b  = blockIdx.x >> 6;
    const int i0 = (blockIdx.x & 63) * 8;
    const int t  = threadIdx.x;

    s2s[t]       = g_s2[b * NN + t];
    s2s[t + 256] = g_s2[b * NN + t + 256];
    __syncthreads();

    const int w = t >> 5, lane = t & 31;
    const int i = i0 + w;
    const float s1v = g_s1[b * NN + i];
    const int* adjrow = adj + (size_t)(b * NN + i) * NN;

    float v[16];
    float m = -INFINITY;
    #pragma unroll
    for (int jj = 0; jj < 16; jj++) {
        const int j = lane + jj * 32;
        const float x = s1v + s2s[j];
        const float e = x > 0.f ? x : SLOPE * x;
        const float val = (adjrow[j] > 0) ? e : NEGV;
        v[jj] = val;
        m = fmaxf(m, val);
    }
    #pragma unroll
    for (int off = 16; off; off >>= 1)
        m = fmaxf(m, __shfl_xor_sync(0xFFFFFFFFu, m, off));

    float s = 0.f;
    #pragma unroll
    for (int jj = 0; jj < 16; jj++) {
        const float ex = __expf(v[jj] - m);
        v[jj] = ex;
        s += ex;
    }
    #pragma unroll
    for (int off = 16; off; off >>= 1)
        s += __shfl_xor_sync(0xFFFFFFFFu, s, off);

    const float inv = 1.f / s;
    float*  arow  = out_att + (size_t)(b * NN + i) * NN;
    __half* arow16 = g_att16 + ((size_t)b * NN + i) * NN;
    #pragma unroll
    for (int jj = 0; jj < 16; jj++) {
        const int j = lane + jj * 32;
        const float av = v[jj] * inv;
        arow[j] = av;
        arow16[j] = __float2half_rn(av);
    }
}

// ---------------------------------------------------------------------------
// Kernel G2: h_prime[b] = att[b] @ Wh[b]   (fp16 MMA, 2-stage pipeline)
// per batch C[512,256] = A[512,512] * B[512,256]; grid 32*4*2 = 256 CTAs
// ---------------------------------------------------------------------------
__global__ void __launch_bounds__(256, 2) k_gemm2(float* __restrict__ out_hp)
{
    extern __shared__ unsigned smem[];

    const int bx   = blockIdx.x;
    const int b    = bx >> 3;
    const int tile = bx & 7;
    const int row0 = (tile >> 1) * BM;
    const int col0 = (tile & 1)  * BN;

    const __half* A16 = g_att16 + (size_t)b * NN * NN;
    const __half* B16 = g_Wht16 + (size_t)b * DOUT * NN;

    const int t    = threadIdx.x;
    const int wid  = t >> 5;
    const int lane = t & 31;
    const int gid  = lane >> 2;
    const int tid4 = lane & 3;
    const int wg   = wid & 3;
    const int wng  = wid >> 2;
    const int wm = wg * 32;
    const int wn = wng * 64;

    float acc[2][8][4];
    #pragma unroll
    for (int i = 0; i < 2; i++)
        #pragma unroll
        for (int j = 0; j < 8; j++)
            #pragma unroll
            for (int q = 0; q < 4; q++)
                acc[i][j][q] = 0.f;

    uint4 av[2], bv[2];
    const int rr = t >> 2;
    const int uu = t & 3;

    const int NTILES = NN / BK;   // 16

    #pragma unroll
    for (int i = 0; i < 2; i++) {
        av[i] = *reinterpret_cast<const uint4*>(
            A16 + (size_t)(row0 + rr + i * 64) * NN + uu * 8);
        bv[i] = *reinterpret_cast<const uint4*>(
            B16 + (size_t)(col0 + rr + i * 64) * NN + uu * 8);
    }
    stage_store(smem, av, bv, rr, uu);
    #pragma unroll
    for (int i = 0; i < 2; i++) {
        av[i] = *reinterpret_cast<const uint4*>(
            A16 + (size_t)(row0 + rr + i * 64) * NN + BK + uu * 8);
        bv[i] = *reinterpret_cast<const uint4*>(
            B16 + (size_t)(col0 + rr + i * 64) * NN + BK + uu * 8);
    }
    __syncthreads();

    for (int tk = 0; tk < NTILES; tk++) {
        unsigned* cur = smem + (tk & 1) * STAGE_U32;
        if (tk + 1 < NTILES) {
            unsigned* nxt = smem + ((tk + 1) & 1) * STAGE_U32;
            stage_store(nxt, av, bv, rr, uu);
        }
        if (tk + 2 < NTILES) {
            const int k0 = (tk + 2) * BK;
            #pragma unroll
            for (int i = 0; i < 2; i++) {
                av[i] = *reinterpret_cast<const uint4*>(
                    A16 + (size_t)(row0 + rr + i * 64) * NN + k0 + uu * 8);
                bv[i] = *reinterpret_cast<const uint4*>(
                    B16 + (size_t)(col0 + rr + i * 64) * NN + k0 + uu * 8);
            }
        }
        stage_mma(cur, acc, wm, wn, gid, tid4);
        __syncthreads();
    }

    float* outB = out_hp + (size_t)b * NN * DOUT;
    #pragma unroll
    for (int ms = 0; ms < 2; ms++) {
        const int r0 = row0 + wm + ms * 16 + gid;
        const int r1 = r0 + 8;
        #pragma unroll
        for (int ns = 0; ns < 8; ns++) {
            const int c = col0 + wn + ns * 8 + tid4 * 2;
            float2 o0, o1;
            o0.x = acc[ms][ns][0];
            o0.y = acc[ms][ns][1];
            o1.x = acc[ms][ns][2];
            o1.y = acc[ms][ns][3];
            *reinterpret_cast<float2*>(&outB[(size_t)r0 * DOUT + c]) = o0;
            *reinterpret_cast<float2*>(&outB[(size_t)r1 * DOUT + c]) = o1;
        }
    }
}

// ---------------------------------------------------------------------------
extern "C" void kernel_launch(void* const* d_in, const int* in_sizes, int n_in,
                              void* d_out, int out_size)
{
    const float* h         = (const float*)d_in[0];
    const int*   adj       = (const int*)  d_in[1];
    const int*   positions = (const int*)  d_in[2];
    const float* W         = (const float*)d_in[3];
    const float* a1        = (const float*)d_in[4];
    const float* a2        = (const float*)d_in[5];
    const float* pos_table = (const float*)d_in[6];

    float* out_hp  = (float*)d_out;                        // [B,N,DOUT]
    float* out_att = (float*)d_out + (size_t)MM * DOUT;    // [B,N,N]

    static bool attr_done = false;
    if (!attr_done) {
        cudaFuncSetAttribute(k_gemm1,
            cudaFuncAttributeMaxDynamicSharedMemorySize, SMEM_BYTES);
        cudaFuncSetAttribute(k_gemm2,
            cudaFuncAttributeMaxDynamicSharedMemorySize, SMEM_BYTES);
        attr_done = true;
    }

    k_prep_h<<<(MM * DIN / 4) / 256, 256>>>(h);
    k_prep_w<<<dim3(DIN / 32, DOUT / 32), dim3(32, 8)>>>(W);
    k_gemm1<<<(MM / BM) * (DOUT / BN), 256, SMEM_BYTES>>>(positions, pos_table);
    k_sdots<<<MM / 8, 256>>>(a1, a2);
    k_prep_wht<<<BB * 128, dim3(32, 8)>>>();
    k_softmax<<<BB * (NN / 8), 256>>>(adj, out_att);
    k_gemm2<<<BB * 8, 256, SMEM_BYTES>>>(out_hp);
}

// round 16
// speedup vs baseline: 3.2741x; 1.2726x over previous
#include <cuda_runtime.h>
#include <cuda_fp16.h>
#include <math.h>
#include <stdint.h>

// Problem constants
#define BB   32
#define NN   512
#define DIN  768
#define DOUT 256
#define MM   (BB * NN)          // 16384 rows
#define NEGV (-9.0e15f)
#define SLOPE 0.2f

// Scratch (device globals: allocation-free)
__device__ float  g_Wh[(size_t)MM * DOUT];          // fp32 Wh (+pos emb)
__device__ float  g_s1[MM];
__device__ float  g_s2[MM];
__device__ __half g_Wt16[(size_t)DOUT * DIN];       // W^T  [256][768] fp16
__device__ __half g_Wht16[(size_t)BB * DOUT * NN];  // Wh^T [b][256][512] fp16
__device__ __half g_att16[(size_t)BB * NN * NN];    // att  [b][512][512] fp16

// ---------------------------------------------------------------------------
// fp16 MMA helper: m16n8k16, fp32 accumulate
// ---------------------------------------------------------------------------
__device__ __forceinline__ void mma_f16(
    float c[4], unsigned a0, unsigned a1, unsigned a2, unsigned a3,
    unsigned b0, unsigned b1)
{
    asm volatile(
        "mma.sync.aligned.m16n8k16.row.col.f32.f16.f16.f32 "
        "{%0,%1,%2,%3}, {%4,%5,%6,%7}, {%8,%9}, {%0,%1,%2,%3};\n"
        : "+f"(c[0]), "+f"(c[1]), "+f"(c[2]), "+f"(c[3])
        : "r"(a0), "r"(a1), "r"(a2), "r"(a3), "r"(b0), "r"(b1));
}

// ---------------------------------------------------------------------------
// GEMM tile geometry: BM=128 BN=128 BK=32, 8 warps (4m x 2n), warp tile 32x64.
// SMEM: [row(128)][k-pairs(16 u32) + pad4], stride 20 u32, conflict-free.
// Double buffered: 2 stages x 20KB = 40KB dynamic smem.
// ---------------------------------------------------------------------------
#define BM 128
#define BN 128
#define BK 32
#define RSTRIDE 20                     // u32 per row (16 data + 4 pad)
#define A_U32   (BM * RSTRIDE)         // 2560
#define STAGE_U32 (2 * A_U32)          // A + B = 5120
#define SMEM_BYTES (2 * STAGE_U32 * 4) // 40960

__device__ __forceinline__ unsigned pack_h2(float x, float y) {
    __half2 p = __floats2half2_rn(x, y);
    return *reinterpret_cast<unsigned*>(&p);
}

// stage copy (pure fp16 source): 2 uint4 for A + 2 uint4 for B per thread
__device__ __forceinline__ void stage_store(
    unsigned* stage, const uint4* av, const uint4* bv, int rr, int uu)
{
    #pragma unroll
    for (int i = 0; i < 2; i++)
        *reinterpret_cast<uint4*>(stage + (rr + i * 64) * RSTRIDE + uu * 4) = av[i];
    #pragma unroll
    for (int i = 0; i < 2; i++)
        *reinterpret_cast<uint4*>(stage + A_U32 + (rr + i * 64) * RSTRIDE + uu * 4) = bv[i];
}

// stage store with fp32->fp16 conversion for A (af: 2 float4 per row chunk)
__device__ __forceinline__ void stage_store_cvt(
    unsigned* stage, const float4* af, const uint4* bv, int rr, int uu)
{
    #pragma unroll
    for (int i = 0; i < 2; i++) {
        uint4 o;
        o.x = pack_h2(af[2 * i].x, af[2 * i].y);
        o.y = pack_h2(af[2 * i].z, af[2 * i].w);
        o.z = pack_h2(af[2 * i + 1].x, af[2 * i + 1].y);
        o.w = pack_h2(af[2 * i + 1].z, af[2 * i + 1].w);
        *reinterpret_cast<uint4*>(stage + (rr + i * 64) * RSTRIDE + uu * 4) = o;
    }
    #pragma unroll
    for (int i = 0; i < 2; i++)
        *reinterpret_cast<uint4*>(stage + A_U32 + (rr + i * 64) * RSTRIDE + uu * 4) = bv[i];
}

// mainloop: 2 k16-steps, warp tile 32x64
__device__ __forceinline__ void stage_mma(
    const unsigned* stage, float acc[2][8][4], int wm, int wn, int gid, int tid4)
{
    const unsigned* Aq = stage;
    const unsigned* Bq = stage + A_U32;
    #pragma unroll
    for (int ks = 0; ks < 2; ks++) {
        const int kc = ks * 8 + tid4;
        unsigned a[2][4];
        #pragma unroll
        for (int ms = 0; ms < 2; ms++) {
            const int r = wm + ms * 16 + gid;
            a[ms][0] = Aq[r * RSTRIDE + kc];
            a[ms][1] = Aq[(r + 8) * RSTRIDE + kc];
            a[ms][2] = Aq[r * RSTRIDE + kc + 4];
            a[ms][3] = Aq[(r + 8) * RSTRIDE + kc + 4];
        }
        #pragma unroll
        for (int ns = 0; ns < 8; ns++) {
            const int c = wn + ns * 8 + gid;
            const unsigned b0 = Bq[c * RSTRIDE + kc];
            const unsigned b1 = Bq[c * RSTRIDE + kc + 4];
            mma_f16(acc[0][ns], a[0][0], a[0][1], a[0][2], a[0][3], b0, b1);
            mma_f16(acc[1][ns], a[1][0], a[1][1], a[1][2], a[1][3], b0, b1);
        }
    }
}

// ---------------------------------------------------------------------------
// prep: W[768][256] fp32 -> W^T fp16 [256][768]   (tiny, one-off)
// ---------------------------------------------------------------------------
__global__ void k_prep_w(const float* __restrict__ W)
{
    __shared__ float tile[32][33];
    const int k0 = blockIdx.x * 32;
    const int n0 = blockIdx.y * 32;
    const int tx = threadIdx.x, ty = threadIdx.y;
    #pragma unroll
    for (int j = 0; j < 4; j++)
        tile[ty + j * 8][tx] = W[(size_t)(k0 + ty + j * 8) * DOUT + n0 + tx];
    __syncthreads();
    #pragma unroll
    for (int j = 0; j < 4; j++)
        g_Wt16[(size_t)(n0 + ty + j * 8) * DIN + k0 + tx] =
            __float2half_rn(tile[tx][ty + j * 8]);
}

// zero the s1/s2 accumulators (required every replay: epilogue atomicAdds)
__global__ void k_zero_s()
{
    const int i = blockIdx.x * 256 + threadIdx.x;
    g_s1[i] = 0.f;
    g_s2[i] = 0.f;
}

// ---------------------------------------------------------------------------
// Kernel A (fused): Wh = h @ W + pos_emb; also emits Wh^T fp16 and partial
// s1/s2 dots (atomicAdd). fp16 MMA, 2-stage pipeline.
// grid 128x2 = 256 CTAs.
// ---------------------------------------------------------------------------
__global__ void __launch_bounds__(256, 2) k_gemm1(
    const float* __restrict__ h,
    const int*   __restrict__ positions,
    const float* __restrict__ pos_table,
    const float* __restrict__ a1,
    const float* __restrict__ a2)
{
    extern __shared__ unsigned smem[];

    const int bx   = blockIdx.x;
    const int row0 = (bx >> 1) * BM;
    const int col0 = (bx & 1)  * BN;
    const int b    = (bx >> 1) >> 2;       // batch = row0 / NN

    const int t    = threadIdx.x;
    const int wid  = t >> 5;
    const int lane = t & 31;
    const int gid  = lane >> 2;
    const int tid4 = lane & 3;
    const int wg   = wid & 3;
    const int wng  = wid >> 2;
    const int wm = wg * 32;
    const int wn = wng * 64;

    float acc[2][8][4];
    #pragma unroll
    for (int i = 0; i < 2; i++)
        #pragma unroll
        for (int j = 0; j < 8; j++)
            #pragma unroll
            for (int q = 0; q < 4; q++)
                acc[i][j][q] = 0.f;

    float4 af[4];
    uint4  bv[2];
    const int rr = t >> 2;        // 0..63
    const int uu = t & 3;

    const int NTILES = DIN / BK;  // 24

    // prologue: tile0 -> stage0; tile1 -> regs
    #pragma unroll
    for (int i = 0; i < 2; i++) {
        const float4* hp = reinterpret_cast<const float4*>(
            &h[(size_t)(row0 + rr + i * 64) * DIN + uu * 8]);
        af[2 * i] = hp[0];
        af[2 * i + 1] = hp[1];
        bv[i] = *reinterpret_cast<const uint4*>(
            g_Wt16 + (size_t)(col0 + rr + i * 64) * DIN + uu * 8);
    }
    stage_store_cvt(smem, af, bv, rr, uu);
    #pragma unroll
    for (int i = 0; i < 2; i++) {
        const float4* hp = reinterpret_cast<const float4*>(
            &h[(size_t)(row0 + rr + i * 64) * DIN + BK + uu * 8]);
        af[2 * i] = hp[0];
        af[2 * i + 1] = hp[1];
        bv[i] = *reinterpret_cast<const uint4*>(
            g_Wt16 + (size_t)(col0 + rr + i * 64) * DIN + BK + uu * 8);
    }
    __syncthreads();

    for (int tile = 0; tile < NTILES; tile++) {
        unsigned* cur = smem + (tile & 1) * STAGE_U32;
        if (tile + 1 < NTILES) {
            unsigned* nxt = smem + ((tile + 1) & 1) * STAGE_U32;
            stage_store_cvt(nxt, af, bv, rr, uu);
        }
        if (tile + 2 < NTILES) {
            const int k0 = (tile + 2) * BK;
            #pragma unroll
            for (int i = 0; i < 2; i++) {
                const float4* hp = reinterpret_cast<const float4*>(
                    &h[(size_t)(row0 + rr + i * 64) * DIN + k0 + uu * 8]);
                af[2 * i] = hp[0];
                af[2 * i + 1] = hp[1];
                bv[i] = *reinterpret_cast<const uint4*>(
                    g_Wt16 + (size_t)(col0 + rr + i * 64) * DIN + k0 + uu * 8);
            }
        }
        stage_mma(cur, acc, wm, wn, gid, tid4);
        __syncthreads();
    }

    // epilogue: pos emb; store Wh fp32; store Wh^T fp16; partial s1/s2
    const int jr0 = row0 - b * NN + wm + gid;     // local j of r0 (ms=0)
    float d1[4] = {0.f, 0.f, 0.f, 0.f};
    float d2[4] = {0.f, 0.f, 0.f, 0.f};

    #pragma unroll
    for (int ms = 0; ms < 2; ms++) {
        const int r0 = row0 + wm + ms * 16 + gid;
        const int r1 = r0 + 8;
        const int p0 = positions[r0];
        const int p1 = positions[r1];
        const int j0 = jr0 + ms * 16;
        const int j1 = j0 + 8;
        #pragma unroll
        for (int ns = 0; ns < 8; ns++) {
            const int c = col0 + wn + ns * 8 + tid4 * 2;
            float2 pe0 = *reinterpret_cast<const float2*>(&pos_table[(size_t)p0 * DOUT + c]);
            float2 pe1 = *reinterpret_cast<const float2*>(&pos_table[(size_t)p1 * DOUT + c]);
            float2 o0, o1;
            o0.x = acc[ms][ns][0] + pe0.x;
            o0.y = acc[ms][ns][1] + pe0.y;
            o1.x = acc[ms][ns][2] + pe1.x;
            o1.y = acc[ms][ns][3] + pe1.y;
            *reinterpret_cast<float2*>(&g_Wh[(size_t)r0 * DOUT + c]) = o0;
            *reinterpret_cast<float2*>(&g_Wh[(size_t)r1 * DOUT + c]) = o1;

            // transposed fp16 copy
            __half* wt = g_Wht16 + ((size_t)b * DOUT + c) * NN;
            wt[j0]      = __float2half_rn(o0.x);
            wt[NN + j0] = __float2half_rn(o0.y);
            wt[j1]      = __float2half_rn(o1.x);
            wt[NN + j1] = __float2half_rn(o1.y);

            // partial dots
            const float a1c = a1[c], a1d = a1[c + 1];
            const float a2c = a2[c], a2d = a2[c + 1];
            d1[ms * 2]     += o0.x * a1c + o0.y * a1d;
            d2[ms * 2]     += o0.x * a2c + o0.y * a2d;
            d1[ms * 2 + 1] += o1.x * a1c + o1.y * a1d;
            d2[ms * 2 + 1] += o1.x * a2c + o1.y * a2d;
        }
    }

    // reduce across the 4 lanes sharing each row (tid4 group), then atomicAdd
    #pragma unroll
    for (int q = 0; q < 4; q++) {
        d1[q] += __shfl_xor_sync(0xFFFFFFFFu, d1[q], 1);
        d1[q] += __shfl_xor_sync(0xFFFFFFFFu, d1[q], 2);
        d2[q] += __shfl_xor_sync(0xFFFFFFFFu, d2[q], 1);
        d2[q] += __shfl_xor_sync(0xFFFFFFFFu, d2[q], 2);
    }
    if (tid4 == 0) {
        #pragma unroll
        for (int q = 0; q < 4; q++) {
            const int row = row0 + wm + (q >> 1) * 16 + (q & 1) * 8 + gid;
            atomicAdd(&g_s1[row], d1[q]);
            atomicAdd(&g_s2[row], d2[q]);
        }
    }
}

// ---------------------------------------------------------------------------
// Kernel SM: masked softmax; writes fp32 att output + fp16 copy (vectorized)
// ---------------------------------------------------------------------------
__global__ void __launch_bounds__(256) k_softmax(
    const int* __restrict__ adj,
    float* __restrict__ out_att)
{
    __shared__ float s2s[NN];

    const int b  = blockIdx.x >> 6;
    const int i0 = (blockIdx.x & 63) * 8;
    const int t  = threadIdx.x;

    s2s[t]       = g_s2[b * NN + t];
    s2s[t + 256] = g_s2[b * NN + t + 256];
    __syncthreads();

    const int w = t >> 5, lane = t & 31;
    const int i = i0 + w;
    const float s1v = g_s1[b * NN + i];
    const int* adjrow = adj + (size_t)(b * NN + i) * NN;

    float v[16];
    float m = -INFINITY;
    #pragma unroll
    for (int jj = 0; jj < 4; jj++) {
        const int j0 = jj * 128 + lane * 4;
        const int4   a4 = *reinterpret_cast<const int4*>(&adjrow[j0]);
        const float4 s4 = *reinterpret_cast<const float4*>(&s2s[j0]);
        const float x0 = s1v + s4.x, x1 = s1v + s4.y;
        const float x2 = s1v + s4.z, x3 = s1v + s4.w;
        const float e0 = x0 > 0.f ? x0 : SLOPE * x0;
        const float e1 = x1 > 0.f ? x1 : SLOPE * x1;
        const float e2 = x2 > 0.f ? x2 : SLOPE * x2;
        const float e3 = x3 > 0.f ? x3 : SLOPE * x3;
        v[jj * 4 + 0] = (a4.x > 0) ? e0 : NEGV;
        v[jj * 4 + 1] = (a4.y > 0) ? e1 : NEGV;
        v[jj * 4 + 2] = (a4.z > 0) ? e2 : NEGV;
        v[jj * 4 + 3] = (a4.w > 0) ? e3 : NEGV;
        m = fmaxf(m, fmaxf(fmaxf(v[jj * 4], v[jj * 4 + 1]),
                           fmaxf(v[jj * 4 + 2], v[jj * 4 + 3])));
    }
    #pragma unroll
    for (int off = 16; off; off >>= 1)
        m = fmaxf(m, __shfl_xor_sync(0xFFFFFFFFu, m, off));

    float s = 0.f;
    #pragma unroll
    for (int q = 0; q < 16; q++) {
        const float ex = __expf(v[q] - m);
        v[q] = ex;
        s += ex;
    }
    #pragma unroll
    for (int off = 16; off; off >>= 1)
        s += __shfl_xor_sync(0xFFFFFFFFu, s, off);

    const float inv = 1.f / s;
    float*  arow   = out_att + (size_t)(b * NN + i) * NN;
    __half* arow16 = g_att16 + ((size_t)b * NN + i) * NN;
    #pragma unroll
    for (int jj = 0; jj < 4; jj++) {
        const int j0 = jj * 128 + lane * 4;
        float4 o;
        o.x = v[jj * 4 + 0] * inv;
        o.y = v[jj * 4 + 1] * inv;
        o.z = v[jj * 4 + 2] * inv;
        o.w = v[jj * 4 + 3] * inv;
        *reinterpret_cast<float4*>(&arow[j0]) = o;
        uint2 h2;
        h2.x = pack_h2(o.x, o.y);
        h2.y = pack_h2(o.z, o.w);
        *reinterpret_cast<uint2*>(&arow16[j0]) = h2;
    }
}

// ---------------------------------------------------------------------------
// Kernel G2: h_prime[b] = att[b] @ Wh[b]   (fp16 MMA, 2-stage pipeline)
// per batch C[512,256] = A[512,512] * B[512,256]; grid 32*4*2 = 256 CTAs
// ---------------------------------------------------------------------------
__global__ void __launch_bounds__(256, 2) k_gemm2(float* __restrict__ out_hp)
{
    extern __shared__ unsigned smem[];

    const int bx   = blockIdx.x;
    const int b    = bx >> 3;
    const int tile = bx & 7;
    const int row0 = (tile >> 1) * BM;
    const int col0 = (tile & 1)  * BN;

    const __half* A16 = g_att16 + (size_t)b * NN * NN;
    const __half* B16 = g_Wht16 + (size_t)b * DOUT * NN;

    const int t    = threadIdx.x;
    const int wid  = t >> 5;
    const int lane = t & 31;
    const int gid  = lane >> 2;
    const int tid4 = lane & 3;
    const int wg   = wid & 3;
    const int wng  = wid >> 2;
    const int wm = wg * 32;
    const int wn = wng * 64;

    float acc[2][8][4];
    #pragma unroll
    for (int i = 0; i < 2; i++)
        #pragma unroll
        for (int j = 0; j < 8; j++)
            #pragma unroll
            for (int q = 0; q < 4; q++)
                acc[i][j][q] = 0.f;

    uint4 av[2], bv[2];
    const int rr = t >> 2;
    const int uu = t & 3;

    const int NTILES = NN / BK;   // 16

    #pragma unroll
    for (int i = 0; i < 2; i++) {
        av[i] = *reinterpret_cast<const uint4*>(
            A16 + (size_t)(row0 + rr + i * 64) * NN + uu * 8);
        bv[i] = *reinterpret_cast<const uint4*>(
            B16 + (size_t)(col0 + rr + i * 64) * NN + uu * 8);
    }
    stage_store(smem, av, bv, rr, uu);
    #pragma unroll
    for (int i = 0; i < 2; i++) {
        av[i] = *reinterpret_cast<const uint4*>(
            A16 + (size_t)(row0 + rr + i * 64) * NN + BK + uu * 8);
        bv[i] = *reinterpret_cast<const uint4*>(
            B16 + (size_t)(col0 + rr + i * 64) * NN + BK + uu * 8);
    }
    __syncthreads();

    for (int tk = 0; tk < NTILES; tk++) {
        unsigned* cur = smem + (tk & 1) * STAGE_U32;
        if (tk + 1 < NTILES) {
            unsigned* nxt = smem + ((tk + 1) & 1) * STAGE_U32;
            stage_store(nxt, av, bv, rr, uu);
        }
        if (tk + 2 < NTILES) {
            const int k0 = (tk + 2) * BK;
            #pragma unroll
            for (int i = 0; i < 2; i++) {
                av[i] = *reinterpret_cast<const uint4*>(
                    A16 + (size_t)(row0 + rr + i * 64) * NN + k0 + uu * 8);
                bv[i] = *reinterpret_cast<const uint4*>(
                    B16 + (size_t)(col0 + rr + i * 64) * NN + k0 + uu * 8);
            }
        }
        stage_mma(cur, acc, wm, wn, gid, tid4);
        __syncthreads();
    }

    float* outB = out_hp + (size_t)b * NN * DOUT;
    #pragma unroll
    for (int ms = 0; ms < 2; ms++) {
        const int r0 = row0 + wm + ms * 16 + gid;
        const int r1 = r0 + 8;
        #pragma unroll
        for (int ns = 0; ns < 8; ns++) {
            const int c = col0 + wn + ns * 8 + tid4 * 2;
            float2 o0, o1;
            o0.x = acc[ms][ns][0];
            o0.y = acc[ms][ns][1];
            o1.x = acc[ms][ns][2];
            o1.y = acc[ms][ns][3];
            *reinterpret_cast<float2*>(&outB[(size_t)r0 * DOUT + c]) = o0;
            *reinterpret_cast<float2*>(&outB[(size_t)r1 * DOUT + c]) = o1;
        }
    }
}

// ---------------------------------------------------------------------------
extern "C" void kernel_launch(void* const* d_in, const int* in_sizes, int n_in,
                              void* d_out, int out_size)
{
    const float* h         = (const float*)d_in[0];
    const int*   adj       = (const int*)  d_in[1];
    const int*   positions = (const int*)  d_in[2];
    const float* W         = (const float*)d_in[3];
    const float* a1        = (const float*)d_in[4];
    const float* a2        = (const float*)d_in[5];
    const float* pos_table = (const float*)d_in[6];

    float* out_hp  = (float*)d_out;                        // [B,N,DOUT]
    float* out_att = (float*)d_out + (size_t)MM * DOUT;    // [B,N,N]

    static bool attr_done = false;
    if (!attr_done) {
        cudaFuncSetAttribute(k_gemm1,
            cudaFuncAttributeMaxDynamicSharedMemorySize, SMEM_BYTES);
        cudaFuncSetAttribute(k_gemm2,
            cudaFuncAttributeMaxDynamicSharedMemorySize, SMEM_BYTES);
        attr_done = true;
    }

    k_prep_w<<<dim3(DIN / 32, DOUT / 32), dim3(32, 8)>>>(W);
    k_zero_s<<<MM / 256, 256>>>();
    k_gemm1<<<(MM / BM) * (DOUT / BN), 256, SMEM_BYTES>>>(
        h, positions, pos_table, a1, a2);
    k_softmax<<<BB * (NN / 8), 256>>>(adj, out_att);
    k_gemm2<<<BB * 8, 256, SMEM_BYTES>>>(out_hp);
}